// round 5
// baseline (speedup 1.0000x reference)
#include <cuda_runtime.h>
#include <cuda_fp16.h>

#define RR 128
#define BASIS 9
#define DATA_DIM 28
#define NUM_STEPS 256
#define STEP_SIZE 0.001f
#define BG 1.0f

#define NVOX (RR*RR*RR)           // 2097152
#define PAD_HALVES 32             // 28 used + 4 pad -> 64B per voxel
#define NBINS 512
#define MAX_RAYS (1 << 20)

// Static scratch (no runtime allocation allowed)
__device__ uint4 g_grid[NVOX * 4];     // fp16 packed grid, 128 MiB
__device__ int   g_perm[MAX_RAYS];
__device__ int   g_keys[MAX_RAYS];
__device__ int   g_hist[NBINS];
__device__ int   g_off[NBINS];

// ---------------------------------------------------------------------------
// Grid conversion: fp32 [NVOX,28] -> fp16 [NVOX,32]. 1 thread per uint4 out.
// ---------------------------------------------------------------------------
__global__ void __launch_bounds__(256)
convert_kernel(const float* __restrict__ tree)
{
    int idx = blockIdx.x * blockDim.x + threadIdx.x;
    if (idx >= NVOX * 4) return;
    int voxel = idx >> 2;
    int q = idx & 3;
    const float4* src = reinterpret_cast<const float4*>(tree) + (size_t)voxel * 7;
    float4 fa, fb;
    if (q < 3) {
        fa = __ldg(src + q * 2);
        fb = __ldg(src + q * 2 + 1);
    } else {
        fa = __ldg(src + 6);
        fb = make_float4(0.f, 0.f, 0.f, 0.f);
    }
    __half2 h0 = __floats2half2_rn(fa.x, fa.y);
    __half2 h1 = __floats2half2_rn(fa.z, fa.w);
    __half2 h2 = __floats2half2_rn(fb.x, fb.y);
    __half2 h3 = __floats2half2_rn(fb.z, fb.w);
    uint4 o;
    o.x = *reinterpret_cast<unsigned*>(&h0);
    o.y = *reinterpret_cast<unsigned*>(&h1);
    o.z = *reinterpret_cast<unsigned*>(&h2);
    o.w = *reinterpret_cast<unsigned*>(&h3);
    g_grid[idx] = o;
}

// ---------------------------------------------------------------------------
// Sorting passes: key = estimated step count, processed longest-first.
// ---------------------------------------------------------------------------
__global__ void zero_hist_kernel()
{
    int i = threadIdx.x;
    if (i < NBINS) { g_hist[i] = 0; }
}

__global__ void __launch_bounds__(256)
key_kernel(const float* __restrict__ origins,
           const float* __restrict__ dirs, int nb)
{
    int i = blockIdx.x * blockDim.x + threadIdx.x;
    if (i >= nb) return;
    float ox = origins[3*i+0], oy = origins[3*i+1], oz = origins[3*i+2];
    float dx = dirs[3*i+0],    dy = dirs[3*i+1],    dz = dirs[3*i+2];
    float inv_norm = rsqrtf(dx*dx + dy*dy + dz*dz);
    dx *= inv_norm; dy *= inv_norm; dz *= inv_norm;
    float idrx = 1.0f / (dx + 1e-9f);
    float idry = 1.0f / (dy + 1e-9f);
    float idrz = 1.0f / (dz + 1e-9f);
    float t1x = -ox * idrx, t2x = t1x + idrx;
    float t1y = -oy * idry, t2y = t1y + idry;
    float t1z = -oz * idrz, t2z = t1z + idrz;
    float tmin = fmaxf(fmaxf(fminf(t1x,t2x), fminf(t1y,t2y)), fminf(t1z,t2z));
    tmin = fmaxf(tmin, 0.0f);
    float tmax = fminf(fminf(fmaxf(t1x,t2x), fmaxf(t1y,t2y)), fmaxf(t1z,t2z));
    tmax = fminf(tmax, 1e9f);

    float m = fmaxf(fmaxf(fabsf(dx), fabsf(dy)), fabsf(dz));
    float dt_est = (1.0f / (float)RR) / m + STEP_SIZE;
    float len = fmaxf(tmax - tmin, 0.0f);
    int steps = (int)fminf(len / dt_est, (float)(NBINS - 1));
    if (!(tmin < tmax)) steps = 0;
    int key = (NBINS - 1) - steps;   // descending length order
    g_keys[i] = key;
    atomicAdd(&g_hist[key], 1);
}

// Single-block exclusive scan of g_hist -> g_off (NBINS <= 1024)
__global__ void __launch_bounds__(NBINS)
scan_kernel()
{
    __shared__ int sm[NBINS];
    int i = threadIdx.x;
    sm[i] = g_hist[i];
    __syncthreads();
    int val = sm[i];
    for (int d = 1; d < NBINS; d <<= 1) {
        int add = (i >= d) ? sm[i - d] : 0;
        __syncthreads();
        sm[i] = val + add;
        __syncthreads();
        val = sm[i];
    }
    g_off[i] = val - g_hist[i];   // exclusive
}

__global__ void __launch_bounds__(256)
scatter_kernel(int nb)
{
    int i = blockIdx.x * blockDim.x + threadIdx.x;
    if (i >= nb) return;
    int key = g_keys[i];
    int pos = atomicAdd(&g_off[key], 1);
    g_perm[pos] = i;
}

// ---------------------------------------------------------------------------
// Main renderer (depth-1 pipeline, permuted ray order)
// ---------------------------------------------------------------------------
__global__ void __launch_bounds__(128)
volrend_kernel(const float* __restrict__ origins,
               const float* __restrict__ dirs,
               const float* __restrict__ viewdirs,
               const float* __restrict__ invradius,
               float* __restrict__ out,
               int nb)
{
    int j = blockIdx.x * blockDim.x + threadIdx.x;
    if (j >= nb) return;
    int i = g_perm[j];

    float ox = origins[3*i+0], oy = origins[3*i+1], oz = origins[3*i+2];
    float dx = dirs[3*i+0],    dy = dirs[3*i+1],    dz = dirs[3*i+2];
    float inv_norm = rsqrtf(dx*dx + dy*dy + dz*dz);
    dx *= inv_norm; dy *= inv_norm; dz *= inv_norm;

    float vx = viewdirs[3*i+0], vy = viewdirs[3*i+1], vz = viewdirs[3*i+2];

    float sh[BASIS];
    sh[0] =  0.28209479177387814f;
    sh[1] = -0.4886025119029199f * vy;
    sh[2] =  0.4886025119029199f * vz;
    sh[3] = -0.4886025119029199f * vx;
    sh[4] =  1.0925484305920792f * vx * vy;
    sh[5] = -1.0925484305920792f * vy * vz;
    sh[6] =  0.31539156525252005f * (2.0f*vz*vz - vx*vx - vy*vy);
    sh[7] = -1.0925484305920792f * vx * vz;
    sh[8] =  0.5462742152960396f * (vx*vx - vy*vy);

    float idrx = 1.0f / (dx + 1e-9f);
    float idry = 1.0f / (dy + 1e-9f);
    float idrz = 1.0f / (dz + 1e-9f);

    float t1x = -ox * idrx, t2x = t1x + idrx;
    float t1y = -oy * idry, t2y = t1y + idry;
    float t1z = -oz * idrz, t2z = t1z + idrz;
    float tmin = fmaxf(fmaxf(fminf(t1x,t2x), fminf(t1y,t2y)), fminf(t1z,t2z));
    tmin = fmaxf(tmin, 0.0f);
    float tmax = fminf(fminf(fmaxf(t1x,t2x), fmaxf(t1y,t2y)), fmaxf(t1z,t2z));
    tmax = fminf(tmax, 1e9f);

    float irx = invradius[0], iry = invradius[1], irz = invradius[2];
    float dsx = dx / irx, dsy = dy / iry, dsz = dz / irz;
    float delta_scale = sqrtf(dsx*dsx + dsy*dsy + dsz*dsz);

    float t = tmin;
    float light = 1.0f;
    float out0 = 0.0f, out1 = 0.0f, out2 = 0.0f;
    const float cube_sz = 1.0f / (float)RR;

    #define GEOM(tt, dt_o, vp_o)                                               \
    {                                                                          \
        float px = fmaf((tt), dx, ox) * (float)RR;                             \
        float py = fmaf((tt), dy, oy) * (float)RR;                             \
        float pz = fmaf((tt), dz, oz) * (float)RR;                             \
        float fx = fminf(fmaxf(floorf(px), 0.0f), (float)(RR-1));              \
        float fy = fminf(fmaxf(floorf(py), 0.0f), (float)(RR-1));              \
        float fz = fminf(fmaxf(floorf(pz), 0.0f), (float)(RR-1));              \
        int flat = (int)fx * (RR*RR) + (int)fy * RR + (int)fz;                 \
        (vp_o) = g_grid + (size_t)flat * 4;                                    \
        float cx = px - fx, cy = py - fy, cz = pz - fz;                        \
        float u1x = -cx * idrx, u2x = u1x + idrx;                              \
        float u1y = -cy * idry, u2y = u1y + idry;                              \
        float u1z = -cz * idrz, u2z = u1z + idrz;                              \
        float s0 = fmaxf(fmaxf(fminf(u1x,u2x), fminf(u1y,u2y)), fminf(u1z,u2z)); \
        s0 = fmaxf(s0, 0.0f);                                                  \
        float s1 = fminf(fminf(fmaxf(u1x,u2x), fmaxf(u1y,u2y)), fmaxf(u1z,u2z)); \
        s1 = fminf(s1, 1e9f);                                                  \
        (dt_o) = (s1 - s0) * cube_sz + STEP_SIZE;                              \
    }

    if (tmin < tmax) {
        float dt_cur;
        const uint4* vp;
        GEOM(t, dt_cur, vp);
        uint4 b0 = __ldg(vp + 0);
        uint4 b1 = __ldg(vp + 1);
        uint4 b2 = __ldg(vp + 2);
        uint4 b3 = __ldg(vp + 3);

        #pragma unroll 1
        for (int s = 0; s < NUM_STEPS; ++s) {
            uint4 a0 = b0, a1 = b1, a2 = b2, a3 = b3;
            float dt = dt_cur;

            float t_new = t + dt;
            bool more = (t_new < tmax) && (s + 1 < NUM_STEPS);
            float dt_next = 0.0f;
            if (more) {
                const uint4* vpn;
                GEOM(t_new, dt_next, vpn);
                b0 = __ldg(vpn + 0);
                b1 = __ldg(vpn + 1);
                b2 = __ldg(vpn + 2);
                b3 = __ldg(vpn + 3);
            }

            __half hs[PAD_HALVES];
            *reinterpret_cast<uint4*>(hs +  0) = a0;
            *reinterpret_cast<uint4*>(hs +  8) = a1;
            *reinterpret_cast<uint4*>(hs + 16) = a2;
            *reinterpret_cast<uint4*>(hs + 24) = a3;

            float sigma = fmaxf(__half2float(hs[27]), 0.0f);
            float att = __expf(-dt * sigma * delta_scale);
            float weight = light * (1.0f - att);

            float c0 = 0.0f, c1 = 0.0f, c2 = 0.0f;
            #pragma unroll
            for (int jj = 0; jj < BASIS; ++jj) {
                c0 = fmaf(sh[jj], __half2float(hs[jj]),            c0);
                c1 = fmaf(sh[jj], __half2float(hs[BASIS + jj]),    c1);
                c2 = fmaf(sh[jj], __half2float(hs[2*BASIS + jj]),  c2);
            }
            float r0 = __fdividef(1.0f, 1.0f + __expf(-c0));
            float r1 = __fdividef(1.0f, 1.0f + __expf(-c1));
            float r2 = __fdividef(1.0f, 1.0f + __expf(-c2));

            out0 = fmaf(weight, r0, out0);
            out1 = fmaf(weight, r1, out1);
            out2 = fmaf(weight, r2, out2);
            light *= att;

            t = t_new;
            dt_cur = dt_next;
            if (!more) break;
        }
    }
    #undef GEOM

    out[3*i+0] = out0 + light * BG;
    out[3*i+1] = out1 + light * BG;
    out[3*i+2] = out2 + light * BG;
}

extern "C" void kernel_launch(void* const* d_in, const int* in_sizes, int n_in,
                              void* d_out, int out_size)
{
    const float* tree      = (const float*)d_in[0];
    const float* origins   = (const float*)d_in[1];
    const float* dirs      = (const float*)d_in[2];
    const float* viewdirs  = (const float*)d_in[3];
    const float* invradius = (const float*)d_in[4];
    float* out = (float*)d_out;

    int nb = in_sizes[1] / 3;

    // Grid repack
    int n_u4 = NVOX * 4;
    convert_kernel<<<(n_u4 + 255) / 256, 256>>>(tree);

    // Ray binning (longest-first)
    zero_hist_kernel<<<1, NBINS>>>();
    key_kernel<<<(nb + 255) / 256, 256>>>(origins, dirs, nb);
    scan_kernel<<<1, NBINS>>>();
    scatter_kernel<<<(nb + 255) / 256, 256>>>(nb);

    // Render
    int threads = 128;
    int blocks = (nb + threads - 1) / threads;
    volrend_kernel<<<blocks, threads>>>(origins, dirs, viewdirs, invradius, out, nb);
}

// round 6
// speedup vs baseline: 1.0858x; 1.0858x over previous
#include <cuda_runtime.h>
#include <cuda_fp16.h>

#define RR 128
#define BASIS 9
#define DATA_DIM 28
#define NUM_STEPS 256
#define STEP_SIZE 0.001f
#define BG 1.0f

#define NVOX (RR*RR*RR)           // 2097152
// 32 halves per voxel, interleaved for HFMA2:
//  halves 0..17 : (c0_j, c1_j) pairs, j = 0..8
//  halves 18..26: c2_0 .. c2_8
//  half  27     : 0 (pad so (c2_8, pad) pair is clean)
//  half  28     : sigma
//  halves 29..31: 0
__device__ uint4 g_grid[NVOX * 4];     // 128 MiB

// ---------------------------------------------------------------------------
// Conversion: fp32 [NVOX,28] -> interleaved fp16 [NVOX,32]. 1 thread / uint4.
// ---------------------------------------------------------------------------
__global__ void __launch_bounds__(256)
convert_kernel(const float* __restrict__ tree)
{
    int idx = blockIdx.x * blockDim.x + threadIdx.x;
    if (idx >= NVOX * 4) return;
    int voxel = idx >> 2;
    int q = idx & 3;
    const float* src = tree + (size_t)voxel * DATA_DIM;

    __half h[8];
    #pragma unroll
    for (int k = 0; k < 8; ++k) {
        int m = q * 8 + k;
        float val;
        if (m < 18)       val = __ldg(src + ((m & 1) ? 9 + (m >> 1) : (m >> 1)));
        else if (m < 27)  val = __ldg(src + m);
        else if (m == 28) val = __ldg(src + 27);
        else              val = 0.0f;
        h[k] = __float2half_rn(val);
    }
    g_grid[idx] = *reinterpret_cast<uint4*>(h);
}

// ---------------------------------------------------------------------------
// Main renderer: depth-1 pipeline + HFMA2 shading
// ---------------------------------------------------------------------------
__global__ void __launch_bounds__(128)
volrend_kernel(const float* __restrict__ origins,
               const float* __restrict__ dirs,
               const float* __restrict__ viewdirs,
               const float* __restrict__ invradius,
               float* __restrict__ out,
               int nb)
{
    int i = blockIdx.x * blockDim.x + threadIdx.x;
    if (i >= nb) return;

    float ox = origins[3*i+0], oy = origins[3*i+1], oz = origins[3*i+2];
    float dx = dirs[3*i+0],    dy = dirs[3*i+1],    dz = dirs[3*i+2];
    float inv_norm = rsqrtf(dx*dx + dy*dy + dz*dz);
    dx *= inv_norm; dy *= inv_norm; dz *= inv_norm;

    float vx = viewdirs[3*i+0], vy = viewdirs[3*i+1], vz = viewdirs[3*i+2];

    float sh[BASIS];
    sh[0] =  0.28209479177387814f;
    sh[1] = -0.4886025119029199f * vy;
    sh[2] =  0.4886025119029199f * vz;
    sh[3] = -0.4886025119029199f * vx;
    sh[4] =  1.0925484305920792f * vx * vy;
    sh[5] = -1.0925484305920792f * vy * vz;
    sh[6] =  0.31539156525252005f * (2.0f*vz*vz - vx*vx - vy*vy);
    sh[7] = -1.0925484305920792f * vx * vz;
    sh[8] =  0.5462742152960396f * (vx*vx - vy*vy);

    // HFMA2 operand packs
    __half2 s01[BASIS];
    #pragma unroll
    for (int j = 0; j < BASIS; ++j) s01[j] = __floats2half2_rn(sh[j], sh[j]);
    __half2 s2[5];
    s2[0] = __floats2half2_rn(sh[0], sh[1]);
    s2[1] = __floats2half2_rn(sh[2], sh[3]);
    s2[2] = __floats2half2_rn(sh[4], sh[5]);
    s2[3] = __floats2half2_rn(sh[6], sh[7]);
    s2[4] = __floats2half2_rn(sh[8], 0.0f);

    float idrx = 1.0f / (dx + 1e-9f);
    float idry = 1.0f / (dy + 1e-9f);
    float idrz = 1.0f / (dz + 1e-9f);

    float t1x = -ox * idrx, t2x = t1x + idrx;
    float t1y = -oy * idry, t2y = t1y + idry;
    float t1z = -oz * idrz, t2z = t1z + idrz;
    float tmin = fmaxf(fmaxf(fminf(t1x,t2x), fminf(t1y,t2y)), fminf(t1z,t2z));
    tmin = fmaxf(tmin, 0.0f);
    float tmax = fminf(fminf(fmaxf(t1x,t2x), fmaxf(t1y,t2y)), fmaxf(t1z,t2z));
    tmax = fminf(tmax, 1e9f);

    float irx = invradius[0], iry = invradius[1], irz = invradius[2];
    float dsx = dx / irx, dsy = dy / iry, dsz = dz / irz;
    float delta_scale = sqrtf(dsx*dsx + dsy*dsy + dsz*dsz);

    // Premultiplied by R for a single-FMA position computation
    float oxR = ox * (float)RR, oyR = oy * (float)RR, ozR = oz * (float)RR;
    float dxR = dx * (float)RR, dyR = dy * (float)RR, dzR = dz * (float)RR;

    float t = tmin;
    float light = 1.0f;
    float out0 = 0.0f, out1 = 0.0f, out2 = 0.0f;
    const float cube_sz = 1.0f / (float)RR;

    #define GEOM(tt, dt_o, vp_o)                                               \
    {                                                                          \
        float px = fmaf((tt), dxR, oxR);                                       \
        float py = fmaf((tt), dyR, oyR);                                       \
        float pz = fmaf((tt), dzR, ozR);                                       \
        float fx = fminf(fmaxf(floorf(px), 0.0f), (float)(RR-1));              \
        float fy = fminf(fmaxf(floorf(py), 0.0f), (float)(RR-1));              \
        float fz = fminf(fmaxf(floorf(pz), 0.0f), (float)(RR-1));              \
        int flat = (int)fmaf(fx, 16384.0f, fmaf(fy, 128.0f, fz));              \
        (vp_o) = g_grid + (size_t)flat * 4;                                    \
        float cx = px - fx, cy = py - fy, cz = pz - fz;                        \
        float u1x = -cx * idrx, u2x = u1x + idrx;                              \
        float u1y = -cy * idry, u2y = u1y + idry;                              \
        float u1z = -cz * idrz, u2z = u1z + idrz;                              \
        float s0 = fmaxf(fmaxf(fminf(u1x,u2x), fminf(u1y,u2y)), fminf(u1z,u2z)); \
        s0 = fmaxf(s0, 0.0f);                                                  \
        float s1 = fminf(fminf(fmaxf(u1x,u2x), fmaxf(u1y,u2y)), fmaxf(u1z,u2z)); \
        s1 = fminf(s1, 1e9f);                                                  \
        (dt_o) = (s1 - s0) * cube_sz + STEP_SIZE;                              \
    }

    if (tmin < tmax) {
        float dt_cur;
        const uint4* vp;
        GEOM(t, dt_cur, vp);
        uint4 b0 = __ldg(vp + 0);
        uint4 b1 = __ldg(vp + 1);
        uint4 b2 = __ldg(vp + 2);
        uint4 b3 = __ldg(vp + 3);

        #pragma unroll 1
        for (int s = 0; s < NUM_STEPS; ++s) {
            uint4 a0 = b0, a1 = b1, a2 = b2, a3 = b3;
            float dt = dt_cur;

            // Prefetch next step before shading
            float t_new = t + dt;
            bool more = (t_new < tmax) && (s + 1 < NUM_STEPS);
            float dt_next = 0.0f;
            if (more) {
                const uint4* vpn;
                GEOM(t_new, dt_next, vpn);
                b0 = __ldg(vpn + 0);
                b1 = __ldg(vpn + 1);
                b2 = __ldg(vpn + 2);
                b3 = __ldg(vpn + 3);
            }

            // Shade: half2 SIMD dot products
            __half2 v[16];
            *reinterpret_cast<uint4*>(v +  0) = a0;
            *reinterpret_cast<uint4*>(v +  4) = a1;
            *reinterpret_cast<uint4*>(v +  8) = a2;
            *reinterpret_cast<uint4*>(v + 12) = a3;

            __half2 acc01 = __floats2half2_rn(0.0f, 0.0f);
            #pragma unroll
            for (int j = 0; j < BASIS; ++j)
                acc01 = __hfma2(s01[j], v[j], acc01);
            __half2 acc2 = __floats2half2_rn(0.0f, 0.0f);
            #pragma unroll
            for (int k = 0; k < 5; ++k)
                acc2 = __hfma2(s2[k], v[9 + k], acc2);

            float2 c01 = __half22float2(acc01);
            float2 c2p = __half22float2(acc2);
            float c2 = c2p.x + c2p.y;

            float sigma = fmaxf(__half2float(__low2half(v[14])), 0.0f);
            float att = __expf(-dt * sigma * delta_scale);
            float weight = light * (1.0f - att);

            float r0 = __fdividef(1.0f, 1.0f + __expf(-c01.x));
            float r1 = __fdividef(1.0f, 1.0f + __expf(-c01.y));
            float r2 = __fdividef(1.0f, 1.0f + __expf(-c2));

            out0 = fmaf(weight, r0, out0);
            out1 = fmaf(weight, r1, out1);
            out2 = fmaf(weight, r2, out2);
            light *= att;

            t = t_new;
            dt_cur = dt_next;
            if (!more) break;
        }
    }
    #undef GEOM

    out[3*i+0] = out0 + light * BG;
    out[3*i+1] = out1 + light * BG;
    out[3*i+2] = out2 + light * BG;
}

extern "C" void kernel_launch(void* const* d_in, const int* in_sizes, int n_in,
                              void* d_out, int out_size)
{
    const float* tree      = (const float*)d_in[0];
    const float* origins   = (const float*)d_in[1];
    const float* dirs      = (const float*)d_in[2];
    const float* viewdirs  = (const float*)d_in[3];
    const float* invradius = (const float*)d_in[4];
    float* out = (float*)d_out;

    int nb = in_sizes[1] / 3;

    int n_u4 = NVOX * 4;
    convert_kernel<<<(n_u4 + 255) / 256, 256>>>(tree);

    int threads = 128;
    int blocks = (nb + threads - 1) / threads;
    volrend_kernel<<<blocks, threads>>>(origins, dirs, viewdirs, invradius, out, nb);
}